// round 9
// baseline (speedup 1.0000x reference)
#include <cuda_runtime.h>
#include <cuda_bf16.h>
#include <cstdint>

// Problem constants (fixed by the dataset)
#define M_MAX   8192
#define K_DIM   4096
#define N_DIM   4096
#define NBASIS  256

// Scratch (static device arrays — no allocation allowed)
__device__ __nv_bfloat16 g_Xhi[M_MAX * K_DIM];
__device__ __nv_bfloat16 g_Xlo[M_MAX * K_DIM];
__device__ __nv_bfloat16 g_Wres[N_DIM * K_DIM];
__device__ __nv_bfloat16 g_Bhi[NBASIS * K_DIM];
__device__ __nv_bfloat16 g_Blo[NBASIS * K_DIM];
__device__ float         g_Pt[NBASIS * M_MAX];   // Pt[basis][m]

// ---------------------------------------------------------------------------
// Prep kernels
// ---------------------------------------------------------------------------

__global__ void prep_x(const float* __restrict__ x,
                       __nv_bfloat16* __restrict__ hi,
                       __nv_bfloat16* __restrict__ lo, int n4) {
    int i = blockIdx.x * blockDim.x + threadIdx.x;
    if (i >= n4) return;
    float4 v = ((const float4*)x)[i];
    __nv_bfloat162 h01 = __floats2bfloat162_rn(v.x, v.y);
    __nv_bfloat162 h23 = __floats2bfloat162_rn(v.z, v.w);
    ((__nv_bfloat162*)hi)[2 * i]     = h01;
    ((__nv_bfloat162*)hi)[2 * i + 1] = h23;
    float l0 = v.x - __bfloat162float(h01.x);
    float l1 = v.y - __bfloat162float(h01.y);
    float l2 = v.z - __bfloat162float(h23.x);
    float l3 = v.w - __bfloat162float(h23.y);
    ((__nv_bfloat162*)lo)[2 * i]     = __floats2bfloat162_rn(l0, l1);
    ((__nv_bfloat162*)lo)[2 * i + 1] = __floats2bfloat162_rn(l2, l3);
}

__global__ void prep_w(const int* __restrict__ q,
                       __nv_bfloat16* __restrict__ w, int n4) {
    int i = blockIdx.x * blockDim.x + threadIdx.x;
    if (i >= n4) return;
    int4 v = ((const int4*)q)[i];
    // q - 128 is an integer in [-128,127]: exactly representable in bf16.
    __nv_bfloat162 w01 = __floats2bfloat162_rn((float)(v.x - 128), (float)(v.y - 128));
    __nv_bfloat162 w23 = __floats2bfloat162_rn((float)(v.z - 128), (float)(v.w - 128));
    ((__nv_bfloat162*)w)[2 * i]     = w01;
    ((__nv_bfloat162*)w)[2 * i + 1] = w23;
}

// ---------------------------------------------------------------------------
// MMA helpers (legacy HMMA pipe: ldmatrix + mma.sync.m16n8k16.bf16 + cp.async)
// ---------------------------------------------------------------------------

__device__ __forceinline__ void ldsm4(uint32_t& r0, uint32_t& r1,
                                      uint32_t& r2, uint32_t& r3, uint32_t a) {
    asm volatile("ldmatrix.sync.aligned.m8n8.x4.shared.b16 {%0,%1,%2,%3}, [%4];"
                 : "=r"(r0), "=r"(r1), "=r"(r2), "=r"(r3) : "r"(a));
}

__device__ __forceinline__ void mma16(float* c, const uint32_t* a, const uint32_t* b) {
    asm volatile(
        "mma.sync.aligned.m16n8k16.row.col.f32.bf16.bf16.f32 "
        "{%0,%1,%2,%3},{%4,%5,%6,%7},{%8,%9},{%0,%1,%2,%3};"
        : "+f"(c[0]), "+f"(c[1]), "+f"(c[2]), "+f"(c[3])
        : "r"(a[0]), "r"(a[1]), "r"(a[2]), "r"(a[3]), "r"(b[0]), "r"(b[1]));
}

__device__ __forceinline__ void cp16(uint32_t s, const void* g) {
    asm volatile("cp.async.cg.shared.global [%0], [%1], 16;" :: "r"(s), "l"(g));
}

#define ASTR 144   // 128B of K (64 bf16) + 16B pad: conflict-free ldmatrix phases

// ---------------------------------------------------------------------------
// Big GEMM (bf16): acc = Xhi[m] . Wres[o]  +  fused bitfield epilogue:
//   y[m][o] = sp[o]*acc + r[o]*Pt[idx[o]][m] + bias[o]
// CTA tile 128x256x64(elems), 256 threads (2x4 warps, warp tile 64x64),
// 3-stage cp.async pipeline.
// ---------------------------------------------------------------------------

__global__ __launch_bounds__(256, 1)
void gemm_big(const __nv_bfloat16* __restrict__ X, const __nv_bfloat16* __restrict__ W,
              float* __restrict__ Y,
              const int* __restrict__ codes, const float* __restrict__ scales,
              const float* __restrict__ bias, const float* __restrict__ Pt,
              int N, int Mtot)
{
    constexpr int BM = 128, BN = 256;            // rows; row = 64 bf16 = 128B
    constexpr int STAGE = (BM + BN) * ASTR;      // 55296
    constexpr int OFF_ST = 4096;
    extern __shared__ char smem[];
    const int tid = threadIdx.x, lane = tid & 31, wid = tid >> 5;
    const int wm = wid & 1, wn = wid >> 1;       // 2 x 4 warps, warp tile 64x64
    const size_t mBase = (size_t)blockIdx.y * BM;
    const size_t nBase = (size_t)blockIdx.x * BN;
    const uint32_t sb = (uint32_t)__cvta_generic_to_shared(smem);

    // decode per-column params into smem
    int*   idx_s = (int*)smem;
    float* r_s   = (float*)smem + BN;
    float* sp_s  = (float*)smem + 2 * BN;
    float* b_s   = (float*)smem + 3 * BN;
    for (int c = tid; c < BN; c += 256) {
        int code = codes[nBase + c];
        idx_s[c] = code & 0xFF;
        r_s[c]   = (float)((code >> 8) & 0xFFFF) * (1.0f / 65535.0f);
        sp_s[c]  = scales[nBase + c] * (1.0f / 127.0f);
        b_s[c]   = bias[nBase + c];
    }

    float acc[4][8][4];
#pragma unroll
    for (int i = 0; i < 4; i++)
#pragma unroll
        for (int j = 0; j < 8; j++)
#pragma unroll
            for (int k = 0; k < 4; k++) acc[i][j][k] = 0.f;

    auto fill = [&](int s, int kt) {
        size_t koff = (size_t)kt * 64;           // elements
        uint32_t base = sb + OFF_ST + s * STAGE;
#pragma unroll
        for (int i = 0; i < 12; i++) {
            int id = tid + i * 256;
            bool isB = id >= BM * 8;
            int li = isB ? id - BM * 8 : id;
            int r = li >> 3, c = li & 7;
            const __nv_bfloat16* src =
                (isB ? W + (nBase + r) * (size_t)K_DIM
                     : X + (mBase + r) * (size_t)K_DIM) + koff + c * 8;
            cp16(base + (isB ? BM * ASTR : 0) + r * ASTR + c * 16, src);
        }
        asm volatile("cp.async.commit_group;" ::: "memory");
    };

    fill(0, 0);
    fill(1, 1);
    const int KT = K_DIM / 64;   // 64
    const int lg = lane >> 3, li = lane & 7;

    for (int kt = 0; kt < KT; kt++) {
        int s = kt % 3;
        asm volatile("cp.async.wait_group 1;" ::: "memory");
        __syncthreads();
        if (kt + 2 < KT) fill((kt + 2) % 3, kt + 2);
        else asm volatile("cp.async.commit_group;" ::: "memory");

        uint32_t Ab = sb + OFF_ST + s * STAGE;
        uint32_t Bb = Ab + BM * ASTR;
#pragma unroll
        for (int k16 = 0; k16 < 4; k16++) {
            int kb = k16 * 32;                   // bytes (16 bf16)
            uint32_t a[4][4], b[8][2];
#pragma unroll
            for (int mt = 0; mt < 4; mt++) {
                int row = wm * 64 + mt * 16 + li + (lg & 1) * 8;
                ldsm4(a[mt][0], a[mt][1], a[mt][2], a[mt][3],
                      Ab + row * ASTR + kb + (lg >> 1) * 16);
            }
#pragma unroll
            for (int g = 0; g < 4; g++) {
                int row = wn * 64 + g * 16 + li + (lg >> 1) * 8;
                uint32_t r0, r1, r2, r3;
                ldsm4(r0, r1, r2, r3, Bb + row * ASTR + kb + (lg & 1) * 16);
                b[2 * g][0] = r0; b[2 * g][1] = r1;
                b[2 * g + 1][0] = r2; b[2 * g + 1][1] = r3;
            }
#pragma unroll
            for (int mt = 0; mt < 4; mt++)
#pragma unroll
                for (int nt = 0; nt < 8; nt++)
                    mma16(acc[mt][nt], a[mt], b[nt]);
        }
    }
    asm volatile("cp.async.wait_group 0;" ::: "memory");
    __syncthreads();

    // Fused epilogue
    const int t4 = lane >> 2, t2 = (lane & 3) * 2;
#pragma unroll
    for (int mt = 0; mt < 4; mt++) {
#pragma unroll
        for (int p = 0; p < 2; p++) {
            size_t m = mBase + wm * 64 + mt * 16 + t4 + p * 8;
#pragma unroll
            for (int nt = 0; nt < 8; nt++) {
                int nl = wn * 64 + nt * 8 + t2;
                size_t n = nBase + nl;
                float v0 = fmaf(sp_s[nl], acc[mt][nt][2 * p + 0],
                           fmaf(r_s[nl],
                                __ldg(&Pt[(size_t)idx_s[nl] * Mtot + m]), b_s[nl]));
                float v1 = fmaf(sp_s[nl + 1], acc[mt][nt][2 * p + 1],
                           fmaf(r_s[nl + 1],
                                __ldg(&Pt[(size_t)idx_s[nl + 1] * Mtot + m]), b_s[nl + 1]));
                *(float2*)(Y + m * (size_t)N + n) = make_float2(v0, v1);
            }
        }
    }
}

// ---------------------------------------------------------------------------
// P GEMM (bf16, 3 passes into one fp32 accumulator):
//   Pt[b][m] = Bhi[b].Xhi[m] + Blo[b].Xhi[m] + Bhi[b].Xlo[m]
// CTA tile 128x128x64, 256 threads (2x4 warps, warp tile 64x32).
// ---------------------------------------------------------------------------

__global__ __launch_bounds__(256, 1)
void gemm_P(const __nv_bfloat16* __restrict__ Bhi, const __nv_bfloat16* __restrict__ Blo,
            const __nv_bfloat16* __restrict__ Xhi, const __nv_bfloat16* __restrict__ Xlo,
            float* __restrict__ Pt, int Mtot)
{
    constexpr int BM = 128, BN = 128;
    constexpr int STAGE = (BM + BN) * ASTR;      // 36864
    extern __shared__ char smem[];
    const int tid = threadIdx.x, lane = tid & 31, wid = tid >> 5;
    const int wm = wid & 1, wn = wid >> 1;       // 2 x 4 warps, warp tile 64x32
    const size_t mBase = (size_t)blockIdx.y * BM;    // basis dim
    const size_t nBase = (size_t)blockIdx.x * BN;    // token dim
    const uint32_t sb = (uint32_t)__cvta_generic_to_shared(smem);

    float acc[4][4][4];
#pragma unroll
    for (int i = 0; i < 4; i++)
#pragma unroll
        for (int j = 0; j < 4; j++)
#pragma unroll
            for (int k = 0; k < 4; k++) acc[i][j][k] = 0.f;

    const __nv_bfloat16* Ap[3] = {Bhi, Blo, Bhi};
    const __nv_bfloat16* Bp[3] = {Xhi, Xhi, Xlo};

    auto fill = [&](int s, int kt) {
        int pass = kt >> 6;                      // 64 k-steps per pass
        const __nv_bfloat16* A = Ap[pass];
        const __nv_bfloat16* B = Bp[pass];
        size_t koff = (size_t)(kt & 63) * 64;
        uint32_t base = sb + s * STAGE;
#pragma unroll
        for (int i = 0; i < 8; i++) {
            int id = tid + i * 256;
            bool isB = id >= BM * 8;
            int li2 = isB ? id - BM * 8 : id;
            int r = li2 >> 3, c = li2 & 7;
            const __nv_bfloat16* src =
                (isB ? B + (nBase + r) * (size_t)K_DIM
                     : A + (mBase + r) * (size_t)K_DIM) + koff + c * 8;
            cp16(base + (isB ? BM * ASTR : 0) + r * ASTR + c * 16, src);
        }
        asm volatile("cp.async.commit_group;" ::: "memory");
    };

    fill(0, 0);
    fill(1, 1);
    const int KT = 3 * (K_DIM / 64);   // 192
    const int lg = lane >> 3, li = lane & 7;

    for (int kt = 0; kt < KT; kt++) {
        int s = kt % 3;
        asm volatile("cp.async.wait_group 1;" ::: "memory");
        __syncthreads();
        if (kt + 2 < KT) fill((kt + 2) % 3, kt + 2);
        else asm volatile("cp.async.commit_group;" ::: "memory");

        uint32_t Ab = sb + s * STAGE;
        uint32_t Bb = Ab + BM * ASTR;
#pragma unroll
        for (int k16 = 0; k16 < 4; k16++) {
            int kb = k16 * 32;
            uint32_t a[4][4], b[4][2];
#pragma unroll
            for (int mt = 0; mt < 4; mt++) {
                int row = wm * 64 + mt * 16 + li + (lg & 1) * 8;
                ldsm4(a[mt][0], a[mt][1], a[mt][2], a[mt][3],
                      Ab + row * ASTR + kb + (lg >> 1) * 16);
            }
#pragma unroll
            for (int g = 0; g < 2; g++) {
                int row = wn * 32 + g * 16 + li + (lg >> 1) * 8;
                uint32_t r0, r1, r2, r3;
                ldsm4(r0, r1, r2, r3, Bb + row * ASTR + kb + (lg & 1) * 16);
                b[2 * g][0] = r0; b[2 * g][1] = r1;
                b[2 * g + 1][0] = r2; b[2 * g + 1][1] = r3;
            }
#pragma unroll
            for (int mt = 0; mt < 4; mt++)
#pragma unroll
                for (int nt = 0; nt < 4; nt++)
                    mma16(acc[mt][nt], a[mt], b[nt]);
        }
    }
    asm volatile("cp.async.wait_group 0;" ::: "memory");
    __syncthreads();

    const int t4 = lane >> 2, t2 = (lane & 3) * 2;
#pragma unroll
    for (int mt = 0; mt < 4; mt++) {
#pragma unroll
        for (int p = 0; p < 2; p++) {
            size_t bg = mBase + wm * 64 + mt * 16 + t4 + p * 8;
#pragma unroll
            for (int nt = 0; nt < 4; nt++) {
                size_t mcol = nBase + wn * 32 + nt * 8 + t2;
                *(float2*)(Pt + bg * (size_t)Mtot + mcol) =
                    make_float2(acc[mt][nt][2 * p + 0], acc[mt][nt][2 * p + 1]);
            }
        }
    }
}

// ---------------------------------------------------------------------------
// Launch
// ---------------------------------------------------------------------------

extern "C" void kernel_launch(void* const* d_in, const int* in_sizes, int n_in,
                              void* d_out, int out_size) {
    const float* x      = (const float*)d_in[0];
    const int*   codes  = (const int*)d_in[1];
    const float* basis  = (const float*)d_in[2];
    const int*   residq = (const int*)d_in[3];
    const float* scales = (const float*)d_in[4];
    const float* bias   = (const float*)d_in[5];
    float*       y      = (float*)d_out;

    int N = in_sizes[1];                 // 4096
    int K = in_sizes[2] / NBASIS;        // 4096
    int M = in_sizes[0] / K;             // 8192

    __nv_bfloat16 *Xhi, *Xlo, *Wres, *Bhi, *Blo;
    float* Pt;
    cudaGetSymbolAddress((void**)&Xhi,  g_Xhi);
    cudaGetSymbolAddress((void**)&Xlo,  g_Xlo);
    cudaGetSymbolAddress((void**)&Wres, g_Wres);
    cudaGetSymbolAddress((void**)&Bhi,  g_Bhi);
    cudaGetSymbolAddress((void**)&Blo,  g_Blo);
    cudaGetSymbolAddress((void**)&Pt,   g_Pt);

    constexpr int SMEM_BIG = 4096 + 3 * (128 + 256) * ASTR;  // 169984
    constexpr int SMEM_P   = 3 * (128 + 128) * ASTR;         // 110592
    cudaFuncSetAttribute(gemm_big, cudaFuncAttributeMaxDynamicSharedMemorySize, SMEM_BIG);
    cudaFuncSetAttribute(gemm_P,   cudaFuncAttributeMaxDynamicSharedMemorySize, SMEM_P);

    // 1) Preprocess: split x and basis into bf16 hi/lo; residual -> exact bf16 ints
    int nx4 = (M * K) / 4;
    prep_x<<<(nx4 + 255) / 256, 256>>>(x, Xhi, Xlo, nx4);
    int nb4 = (NBASIS * K) / 4;
    prep_x<<<(nb4 + 255) / 256, 256>>>(basis, Bhi, Blo, nb4);
    int nw4 = (N * K) / 4;
    prep_w<<<(nw4 + 255) / 256, 256>>>(residq, Wres, nw4);

    // 2) P GEMM (transposed): Pt[b][m] = Bhi.Xhi + Blo.Xhi + Bhi.Xlo
    gemm_P<<<dim3(M / 128, NBASIS / 128), 256, SMEM_P>>>(
        Bhi, Blo, Xhi, Xlo, Pt, M);

    // 3) Big GEMM + fused bitfield epilogue:
    //    y[m][o] = (scales[o]/127)*(Xhi.Wres[o]) + r[o]*Pt[idx[o]][m] + bias[o]
    gemm_big<<<dim3(N / 256, M / 128), 256, SMEM_BIG>>>(
        Xhi, Wres, y, codes, scales, bias, Pt, N, M);
}

// round 10
// speedup vs baseline: 1.1534x; 1.1534x over previous
#include <cuda_runtime.h>
#include <cuda_bf16.h>
#include <cstdint>

// Problem constants (fixed by the dataset)
#define M_MAX   8192
#define K_DIM   4096
#define N_DIM   4096
#define NBASIS  256

// Scratch (static device arrays — no allocation allowed)
__device__ __nv_bfloat16 g_Xhi[M_MAX * K_DIM];
__device__ __nv_bfloat16 g_Xlo[M_MAX * K_DIM];
__device__ __nv_bfloat16 g_Wres[N_DIM * K_DIM];
__device__ __nv_bfloat16 g_Bhi[NBASIS * K_DIM];
__device__ __nv_bfloat16 g_Blo[NBASIS * K_DIM];
__device__ float         g_Pt[NBASIS * M_MAX];   // Pt[basis][m]

// ---------------------------------------------------------------------------
// Prep kernels
// ---------------------------------------------------------------------------

__global__ void prep_x(const float* __restrict__ x,
                       __nv_bfloat16* __restrict__ hi,
                       __nv_bfloat16* __restrict__ lo, int n4) {
    int i = blockIdx.x * blockDim.x + threadIdx.x;
    if (i >= n4) return;
    float4 v = ((const float4*)x)[i];
    __nv_bfloat162 h01 = __floats2bfloat162_rn(v.x, v.y);
    __nv_bfloat162 h23 = __floats2bfloat162_rn(v.z, v.w);
    ((__nv_bfloat162*)hi)[2 * i]     = h01;
    ((__nv_bfloat162*)hi)[2 * i + 1] = h23;
    float l0 = v.x - __bfloat162float(h01.x);
    float l1 = v.y - __bfloat162float(h01.y);
    float l2 = v.z - __bfloat162float(h23.x);
    float l3 = v.w - __bfloat162float(h23.y);
    ((__nv_bfloat162*)lo)[2 * i]     = __floats2bfloat162_rn(l0, l1);
    ((__nv_bfloat162*)lo)[2 * i + 1] = __floats2bfloat162_rn(l2, l3);
}

__global__ void prep_w(const int* __restrict__ q,
                       __nv_bfloat16* __restrict__ w, int n4) {
    int i = blockIdx.x * blockDim.x + threadIdx.x;
    if (i >= n4) return;
    int4 v = ((const int4*)q)[i];
    // q - 128 is an integer in [-128,127]: exactly representable in bf16.
    __nv_bfloat162 w01 = __floats2bfloat162_rn((float)(v.x - 128), (float)(v.y - 128));
    __nv_bfloat162 w23 = __floats2bfloat162_rn((float)(v.z - 128), (float)(v.w - 128));
    ((__nv_bfloat162*)w)[2 * i]     = w01;
    ((__nv_bfloat162*)w)[2 * i + 1] = w23;
}

// ---------------------------------------------------------------------------
// MMA helpers (legacy HMMA pipe: ldmatrix + mma.sync.m16n8k16.bf16 + cp.async)
// ---------------------------------------------------------------------------

__device__ __forceinline__ void ldsm4(uint32_t& r0, uint32_t& r1,
                                      uint32_t& r2, uint32_t& r3, uint32_t a) {
    asm volatile("ldmatrix.sync.aligned.m8n8.x4.shared.b16 {%0,%1,%2,%3}, [%4];"
                 : "=r"(r0), "=r"(r1), "=r"(r2), "=r"(r3) : "r"(a));
}

__device__ __forceinline__ void mma16(float* c, const uint32_t* a, const uint32_t* b) {
    asm volatile(
        "mma.sync.aligned.m16n8k16.row.col.f32.bf16.bf16.f32 "
        "{%0,%1,%2,%3},{%4,%5,%6,%7},{%8,%9},{%0,%1,%2,%3};"
        : "+f"(c[0]), "+f"(c[1]), "+f"(c[2]), "+f"(c[3])
        : "r"(a[0]), "r"(a[1]), "r"(a[2]), "r"(a[3]), "r"(b[0]), "r"(b[1]));
}

__device__ __forceinline__ void cp16(uint32_t s, const void* g) {
    asm volatile("cp.async.cg.shared.global [%0], [%1], 16;" :: "r"(s), "l"(g));
}

#define ASTR 144   // 128B of K (64 bf16) + 16B pad: conflict-free ldmatrix phases

// Fragment loaders for a 64x64 warp tile (one k16 chunk at byte offset kb).
// a: 4 frags x 4 regs; b: 8 frags x 2 regs (loaded pairwise via ldsm.x4).
__device__ __forceinline__ void ldfragsA(uint32_t (*a)[4], uint32_t Ab, int rowBase,
                                         int kb, int lg, int li) {
#pragma unroll
    for (int mt = 0; mt < 4; mt++) {
        int row = rowBase + mt * 16 + li + (lg & 1) * 8;
        ldsm4(a[mt][0], a[mt][1], a[mt][2], a[mt][3],
              Ab + row * ASTR + kb + (lg >> 1) * 16);
    }
}
__device__ __forceinline__ void ldfragsB(uint32_t (*b)[2], uint32_t Bb, int rowBase,
                                         int kb, int lg, int li) {
#pragma unroll
    for (int g = 0; g < 4; g++) {
        int row = rowBase + g * 16 + li + (lg >> 1) * 8;
        uint32_t r0, r1, r2, r3;
        ldsm4(r0, r1, r2, r3, Bb + row * ASTR + kb + (lg & 1) * 16);
        b[2 * g][0] = r0; b[2 * g][1] = r1;
        b[2 * g + 1][0] = r2; b[2 * g + 1][1] = r3;
    }
}

// ---------------------------------------------------------------------------
// Big GEMM (bf16): acc = Xhi[m] . Wres[o]  +  fused bitfield epilogue:
//   y[m][o] = sp[o]*acc + r[o]*Pt[idx[o]][m] + bias[o]
// CTA tile 128x128x64(elems), 128 threads (2x2 warps, warp tile 64x64),
// 3-stage cp.async pipeline, register-double-buffered fragments,
// 2 CTAs per SM.
// ---------------------------------------------------------------------------

__global__ __launch_bounds__(128, 2)
void gemm_big(const __nv_bfloat16* __restrict__ X, const __nv_bfloat16* __restrict__ W,
              float* __restrict__ Y,
              const int* __restrict__ codes, const float* __restrict__ scales,
              const float* __restrict__ bias, const float* __restrict__ Pt,
              int N, int Mtot)
{
    constexpr int BM = 128, BN = 128;            // rows; row = 64 bf16 = 128B
    constexpr int STAGE = (BM + BN) * ASTR;      // 36864
    constexpr int OFF_ST = 2048;
    extern __shared__ char smem[];
    const int tid = threadIdx.x, lane = tid & 31, wid = tid >> 5;
    const int wm = wid & 1, wn = wid >> 1;       // 2 x 2 warps, warp tile 64x64
    const size_t mBase = (size_t)blockIdx.y * BM;
    const size_t nBase = (size_t)blockIdx.x * BN;
    const uint32_t sb = (uint32_t)__cvta_generic_to_shared(smem);

    // decode per-column params into smem
    int*   idx_s = (int*)smem;
    float* r_s   = (float*)smem + BN;
    float* sp_s  = (float*)smem + 2 * BN;
    float* b_s   = (float*)smem + 3 * BN;
    for (int c = tid; c < BN; c += 128) {
        int code = codes[nBase + c];
        idx_s[c] = code & 0xFF;
        r_s[c]   = (float)((code >> 8) & 0xFFFF) * (1.0f / 65535.0f);
        sp_s[c]  = scales[nBase + c] * (1.0f / 127.0f);
        b_s[c]   = bias[nBase + c];
    }

    float acc[4][8][4];
#pragma unroll
    for (int i = 0; i < 4; i++)
#pragma unroll
        for (int j = 0; j < 8; j++)
#pragma unroll
            for (int k = 0; k < 4; k++) acc[i][j][k] = 0.f;

    auto fill = [&](int s, int kt) {
        size_t koff = (size_t)kt * 64;           // elements
        uint32_t base = sb + OFF_ST + s * STAGE;
#pragma unroll
        for (int i = 0; i < 16; i++) {
            int id = tid + i * 128;
            bool isB = id >= BM * 8;
            int li2 = isB ? id - BM * 8 : id;
            int r = li2 >> 3, c = li2 & 7;
            const __nv_bfloat16* src =
                (isB ? W + (nBase + r) * (size_t)K_DIM
                     : X + (mBase + r) * (size_t)K_DIM) + koff + c * 8;
            cp16(base + (isB ? BM * ASTR : 0) + r * ASTR + c * 16, src);
        }
        asm volatile("cp.async.commit_group;" ::: "memory");
    };

    fill(0, 0);
    fill(1, 1);
    const int KT = K_DIM / 64;   // 64
    const int lg = lane >> 3, li = lane & 7;
    const int aRow = wm * 64, bRow = wn * 64;

    for (int kt = 0; kt < KT; kt++) {
        int s = kt % 3;
        asm volatile("cp.async.wait_group 1;" ::: "memory");
        __syncthreads();
        if (kt + 2 < KT) fill((kt + 2) % 3, kt + 2);
        else asm volatile("cp.async.commit_group;" ::: "memory");

        uint32_t Ab = sb + OFF_ST + s * STAGE;
        uint32_t Bb = Ab + BM * ASTR;

        uint32_t a[2][4][4], b[2][8][2];
        ldfragsA(a[0], Ab, aRow, 0, lg, li);
        ldfragsB(b[0], Bb, bRow, 0, lg, li);
#pragma unroll
        for (int k16 = 0; k16 < 4; k16++) {
            int cur = k16 & 1, nxt = cur ^ 1;
            if (k16 < 3) {
                ldfragsA(a[nxt], Ab, aRow, (k16 + 1) * 32, lg, li);
                ldfragsB(b[nxt], Bb, bRow, (k16 + 1) * 32, lg, li);
            }
#pragma unroll
            for (int mt = 0; mt < 4; mt++)
#pragma unroll
                for (int nt = 0; nt < 8; nt++)
                    mma16(acc[mt][nt], a[cur][mt], b[cur][nt]);
        }
    }
    asm volatile("cp.async.wait_group 0;" ::: "memory");
    __syncthreads();

    // Fused epilogue
    const int t4 = lane >> 2, t2 = (lane & 3) * 2;
#pragma unroll
    for (int mt = 0; mt < 4; mt++) {
#pragma unroll
        for (int p = 0; p < 2; p++) {
            size_t m = mBase + wm * 64 + mt * 16 + t4 + p * 8;
#pragma unroll
            for (int nt = 0; nt < 8; nt++) {
                int nl = wn * 64 + nt * 8 + t2;
                size_t n = nBase + nl;
                float v0 = fmaf(sp_s[nl], acc[mt][nt][2 * p + 0],
                           fmaf(r_s[nl],
                                __ldg(&Pt[(size_t)idx_s[nl] * Mtot + m]), b_s[nl]));
                float v1 = fmaf(sp_s[nl + 1], acc[mt][nt][2 * p + 1],
                           fmaf(r_s[nl + 1],
                                __ldg(&Pt[(size_t)idx_s[nl + 1] * Mtot + m]), b_s[nl + 1]));
                *(float2*)(Y + m * (size_t)N + n) = make_float2(v0, v1);
            }
        }
    }
}

// ---------------------------------------------------------------------------
// P GEMM (bf16, 3 passes into one fp32 accumulator):
//   Pt[b][m] = Bhi[b].Xhi[m] + Blo[b].Xhi[m] + Bhi[b].Xlo[m]
// CTA tile 128x128x64, 128 threads (2x2 warps, warp tile 64x64), 2 CTAs/SM.
// ---------------------------------------------------------------------------

__global__ __launch_bounds__(128, 2)
void gemm_P(const __nv_bfloat16* __restrict__ Bhi, const __nv_bfloat16* __restrict__ Blo,
            const __nv_bfloat16* __restrict__ Xhi, const __nv_bfloat16* __restrict__ Xlo,
            float* __restrict__ Pt, int Mtot)
{
    constexpr int BM = 128, BN = 128;
    constexpr int STAGE = (BM + BN) * ASTR;      // 36864
    extern __shared__ char smem[];
    const int tid = threadIdx.x, lane = tid & 31, wid = tid >> 5;
    const int wm = wid & 1, wn = wid >> 1;       // 2 x 2 warps, warp tile 64x64
    const size_t mBase = (size_t)blockIdx.y * BM;    // basis dim
    const size_t nBase = (size_t)blockIdx.x * BN;    // token dim
    const uint32_t sb = (uint32_t)__cvta_generic_to_shared(smem);

    float acc[4][8][4];
#pragma unroll
    for (int i = 0; i < 4; i++)
#pragma unroll
        for (int j = 0; j < 8; j++)
#pragma unroll
            for (int k = 0; k < 4; k++) acc[i][j][k] = 0.f;

    const __nv_bfloat16* Ap[3] = {Bhi, Blo, Bhi};
    const __nv_bfloat16* Bp[3] = {Xhi, Xhi, Xlo};

    auto fill = [&](int s, int kt) {
        int pass = kt >> 6;                      // 64 k-steps per pass
        const __nv_bfloat16* A = Ap[pass];
        const __nv_bfloat16* B = Bp[pass];
        size_t koff = (size_t)(kt & 63) * 64;
        uint32_t base = sb + s * STAGE;
#pragma unroll
        for (int i = 0; i < 16; i++) {
            int id = tid + i * 128;
            bool isB = id >= BM * 8;
            int li2 = isB ? id - BM * 8 : id;
            int r = li2 >> 3, c = li2 & 7;
            const __nv_bfloat16* src =
                (isB ? B + (nBase + r) * (size_t)K_DIM
                     : A + (mBase + r) * (size_t)K_DIM) + koff + c * 8;
            cp16(base + (isB ? BM * ASTR : 0) + r * ASTR + c * 16, src);
        }
        asm volatile("cp.async.commit_group;" ::: "memory");
    };

    fill(0, 0);
    fill(1, 1);
    const int KT = 3 * (K_DIM / 64);   // 192
    const int lg = lane >> 3, li = lane & 7;
    const int aRow = wm * 64, bRow = wn * 64;

    for (int kt = 0; kt < KT; kt++) {
        int s = kt % 3;
        asm volatile("cp.async.wait_group 1;" ::: "memory");
        __syncthreads();
        if (kt + 2 < KT) fill((kt + 2) % 3, kt + 2);
        else asm volatile("cp.async.commit_group;" ::: "memory");

        uint32_t Ab = sb + s * STAGE;
        uint32_t Bb = Ab + BM * ASTR;

        uint32_t a[2][4][4], b[2][8][2];
        ldfragsA(a[0], Ab, aRow, 0, lg, li);
        ldfragsB(b[0], Bb, bRow, 0, lg, li);
#pragma unroll
        for (int k16 = 0; k16 < 4; k16++) {
            int cur = k16 & 1, nxt = cur ^ 1;
            if (k16 < 3) {
                ldfragsA(a[nxt], Ab, aRow, (k16 + 1) * 32, lg, li);
                ldfragsB(b[nxt], Bb, bRow, (k16 + 1) * 32, lg, li);
            }
#pragma unroll
            for (int mt = 0; mt < 4; mt++)
#pragma unroll
                for (int nt = 0; nt < 8; nt++)
                    mma16(acc[mt][nt], a[cur][mt], b[cur][nt]);
        }
    }
    asm volatile("cp.async.wait_group 0;" ::: "memory");
    __syncthreads();

    const int t4 = lane >> 2, t2 = (lane & 3) * 2;
#pragma unroll
    for (int mt = 0; mt < 4; mt++) {
#pragma unroll
        for (int p = 0; p < 2; p++) {
            size_t bg = mBase + wm * 64 + mt * 16 + t4 + p * 8;
#pragma unroll
            for (int nt = 0; nt < 8; nt++) {
                size_t mcol = nBase + wn * 64 + nt * 8 + t2;
                *(float2*)(Pt + bg * (size_t)Mtot + mcol) =
                    make_float2(acc[mt][nt][2 * p + 0], acc[mt][nt][2 * p + 1]);
            }
        }
    }
}

// ---------------------------------------------------------------------------
// Launch
// ---------------------------------------------------------------------------

extern "C" void kernel_launch(void* const* d_in, const int* in_sizes, int n_in,
                              void* d_out, int out_size) {
    const float* x      = (const float*)d_in[0];
    const int*   codes  = (const int*)d_in[1];
    const float* basis  = (const float*)d_in[2];
    const int*   residq = (const int*)d_in[3];
    const float* scales = (const float*)d_in[4];
    const float* bias   = (const float*)d_in[5];
    float*       y      = (float*)d_out;

    int N = in_sizes[1];                 // 4096
    int K = in_sizes[2] / NBASIS;        // 4096
    int M = in_sizes[0] / K;             // 8192

    __nv_bfloat16 *Xhi, *Xlo, *Wres, *Bhi, *Blo;
    float* Pt;
    cudaGetSymbolAddress((void**)&Xhi,  g_Xhi);
    cudaGetSymbolAddress((void**)&Xlo,  g_Xlo);
    cudaGetSymbolAddress((void**)&Wres, g_Wres);
    cudaGetSymbolAddress((void**)&Bhi,  g_Bhi);
    cudaGetSymbolAddress((void**)&Blo,  g_Blo);
    cudaGetSymbolAddress((void**)&Pt,   g_Pt);

    constexpr int SMEM_BIG = 2048 + 3 * (128 + 128) * ASTR;  // 112640
    constexpr int SMEM_P   = 3 * (128 + 128) * ASTR;         // 110592
    cudaFuncSetAttribute(gemm_big, cudaFuncAttributeMaxDynamicSharedMemorySize, SMEM_BIG);
    cudaFuncSetAttribute(gemm_P,   cudaFuncAttributeMaxDynamicSharedMemorySize, SMEM_P);

    // 1) Preprocess: split x and basis into bf16 hi/lo; residual -> exact bf16 ints
    int nx4 = (M * K) / 4;
    prep_x<<<(nx4 + 255) / 256, 256>>>(x, Xhi, Xlo, nx4);
    int nb4 = (NBASIS * K) / 4;
    prep_x<<<(nb4 + 255) / 256, 256>>>(basis, Bhi, Blo, nb4);
    int nw4 = (N * K) / 4;
    prep_w<<<(nw4 + 255) / 256, 256>>>(residq, Wres, nw4);

    // 2) P GEMM (transposed): Pt[b][m] = Bhi.Xhi + Blo.Xhi + Bhi.Xlo
    gemm_P<<<dim3(M / 128, NBASIS / 128), 128, SMEM_P>>>(
        Bhi, Blo, Xhi, Xlo, Pt, M);

    // 3) Big GEMM + fused bitfield epilogue:
    //    y[m][o] = (scales[o]/127)*(Xhi.Wres[o]) + r[o]*Pt[idx[o]][m] + bias[o]
    gemm_big<<<dim3(N / 128, M / 128), 128, SMEM_BIG>>>(
        Xhi, Wres, y, codes, scales, bias, Pt, N, M);
}

// round 11
// speedup vs baseline: 1.1602x; 1.0059x over previous
#include <cuda_runtime.h>
#include <cuda_bf16.h>
#include <cstdint>

// Problem constants (fixed by the dataset)
#define M_MAX   8192
#define K_DIM   4096
#define N_DIM   4096
#define NBASIS  256

// Scratch (static device arrays — no allocation allowed)
__device__ __nv_bfloat16 g_Xhi[M_MAX * K_DIM];
__device__ __nv_bfloat16 g_Xlo[M_MAX * K_DIM];
__device__ __nv_bfloat16 g_Wres[N_DIM * K_DIM];
__device__ __nv_bfloat16 g_Bhi[NBASIS * K_DIM];
__device__ __nv_bfloat16 g_Blo[NBASIS * K_DIM];
__device__ float         g_Pt [NBASIS * M_MAX];  // Pt[basis][m] (final)
__device__ float         g_PtA[NBASIS * M_MAX];  // split-K partial 0
__device__ float         g_PtB[NBASIS * M_MAX];  // split-K partial 1

// ---------------------------------------------------------------------------
// Prep kernels
// ---------------------------------------------------------------------------

__global__ void prep_x(const float* __restrict__ x,
                       __nv_bfloat16* __restrict__ hi,
                       __nv_bfloat16* __restrict__ lo, int n4) {
    int i = blockIdx.x * blockDim.x + threadIdx.x;
    if (i >= n4) return;
    float4 v = ((const float4*)x)[i];
    __nv_bfloat162 h01 = __floats2bfloat162_rn(v.x, v.y);
    __nv_bfloat162 h23 = __floats2bfloat162_rn(v.z, v.w);
    ((__nv_bfloat162*)hi)[2 * i]     = h01;
    ((__nv_bfloat162*)hi)[2 * i + 1] = h23;
    float l0 = v.x - __bfloat162float(h01.x);
    float l1 = v.y - __bfloat162float(h01.y);
    float l2 = v.z - __bfloat162float(h23.x);
    float l3 = v.w - __bfloat162float(h23.y);
    ((__nv_bfloat162*)lo)[2 * i]     = __floats2bfloat162_rn(l0, l1);
    ((__nv_bfloat162*)lo)[2 * i + 1] = __floats2bfloat162_rn(l2, l3);
}

__global__ void prep_w(const int* __restrict__ q,
                       __nv_bfloat16* __restrict__ w, int n4) {
    int i = blockIdx.x * blockDim.x + threadIdx.x;
    if (i >= n4) return;
    int4 v = ((const int4*)q)[i];
    // q - 128 is an integer in [-128,127]: exactly representable in bf16.
    __nv_bfloat162 w01 = __floats2bfloat162_rn((float)(v.x - 128), (float)(v.y - 128));
    __nv_bfloat162 w23 = __floats2bfloat162_rn((float)(v.z - 128), (float)(v.w - 128));
    ((__nv_bfloat162*)w)[2 * i]     = w01;
    ((__nv_bfloat162*)w)[2 * i + 1] = w23;
}

// Pt = PtA + PtB (split-K reduction)
__global__ void reduce_Pt(const float* __restrict__ a, const float* __restrict__ b,
                          float* __restrict__ out, int n4) {
    int i = blockIdx.x * blockDim.x + threadIdx.x;
    if (i >= n4) return;
    float4 va = ((const float4*)a)[i];
    float4 vb = ((const float4*)b)[i];
    va.x += vb.x; va.y += vb.y; va.z += vb.z; va.w += vb.w;
    ((float4*)out)[i] = va;
}

// ---------------------------------------------------------------------------
// MMA helpers (legacy HMMA pipe: ldmatrix + mma.sync.m16n8k16.bf16 + cp.async)
// ---------------------------------------------------------------------------

__device__ __forceinline__ void ldsm4(uint32_t& r0, uint32_t& r1,
                                      uint32_t& r2, uint32_t& r3, uint32_t a) {
    asm volatile("ldmatrix.sync.aligned.m8n8.x4.shared.b16 {%0,%1,%2,%3}, [%4];"
                 : "=r"(r0), "=r"(r1), "=r"(r2), "=r"(r3) : "r"(a));
}

__device__ __forceinline__ void mma16(float* c, const uint32_t* a, const uint32_t* b) {
    asm volatile(
        "mma.sync.aligned.m16n8k16.row.col.f32.bf16.bf16.f32 "
        "{%0,%1,%2,%3},{%4,%5,%6,%7},{%8,%9},{%0,%1,%2,%3};"
        : "+f"(c[0]), "+f"(c[1]), "+f"(c[2]), "+f"(c[3])
        : "r"(a[0]), "r"(a[1]), "r"(a[2]), "r"(a[3]), "r"(b[0]), "r"(b[1]));
}

__device__ __forceinline__ void cp16(uint32_t s, const void* g) {
    asm volatile("cp.async.cg.shared.global [%0], [%1], 16;" :: "r"(s), "l"(g));
}

#define ASTR 144   // 128B of K (64 bf16) + 16B pad: conflict-free ldmatrix phases

// Fragment loaders for a 64x64 warp tile (one k16 chunk at byte offset kb).
__device__ __forceinline__ void ldfragsA(uint32_t (*a)[4], uint32_t Ab, int rowBase,
                                         int kb, int lg, int li) {
#pragma unroll
    for (int mt = 0; mt < 4; mt++) {
        int row = rowBase + mt * 16 + li + (lg & 1) * 8;
        ldsm4(a[mt][0], a[mt][1], a[mt][2], a[mt][3],
              Ab + row * ASTR + kb + (lg >> 1) * 16);
    }
}
__device__ __forceinline__ void ldfragsB(uint32_t (*b)[2], uint32_t Bb, int rowBase,
                                         int kb, int lg, int li) {
#pragma unroll
    for (int g = 0; g < 4; g++) {
        int row = rowBase + g * 16 + li + (lg >> 1) * 8;
        uint32_t r0, r1, r2, r3;
        ldsm4(r0, r1, r2, r3, Bb + row * ASTR + kb + (lg & 1) * 16);
        b[2 * g][0] = r0; b[2 * g][1] = r1;
        b[2 * g + 1][0] = r2; b[2 * g + 1][1] = r3;
    }
}

// ---------------------------------------------------------------------------
// Big GEMM (bf16): acc = Xhi[m] . Wres[o]  +  fused bitfield epilogue:
//   y[m][o] = sp[o]*acc + r[o]*Pt[idx[o]][m] + bias[o]
// CTA tile 128x128x64(elems), 128 threads (2x2 warps, warp tile 64x64),
// 3-stage cp.async pipeline, register-double-buffered fragments, 2 CTAs/SM.
// (unchanged from R10 — proven config)
// ---------------------------------------------------------------------------

__global__ __launch_bounds__(128, 2)
void gemm_big(const __nv_bfloat16* __restrict__ X, const __nv_bfloat16* __restrict__ W,
              float* __restrict__ Y,
              const int* __restrict__ codes, const float* __restrict__ scales,
              const float* __restrict__ bias, const float* __restrict__ Pt,
              int N, int Mtot)
{
    constexpr int BM = 128, BN = 128;            // rows; row = 64 bf16 = 128B
    constexpr int STAGE = (BM + BN) * ASTR;      // 36864
    constexpr int OFF_ST = 2048;
    extern __shared__ char smem[];
    const int tid = threadIdx.x, lane = tid & 31, wid = tid >> 5;
    const int wm = wid & 1, wn = wid >> 1;       // 2 x 2 warps, warp tile 64x64
    const size_t mBase = (size_t)blockIdx.y * BM;
    const size_t nBase = (size_t)blockIdx.x * BN;
    const uint32_t sb = (uint32_t)__cvta_generic_to_shared(smem);

    // decode per-column params into smem
    int*   idx_s = (int*)smem;
    float* r_s   = (float*)smem + BN;
    float* sp_s  = (float*)smem + 2 * BN;
    float* b_s   = (float*)smem + 3 * BN;
    for (int c = tid; c < BN; c += 128) {
        int code = codes[nBase + c];
        idx_s[c] = code & 0xFF;
        r_s[c]   = (float)((code >> 8) & 0xFFFF) * (1.0f / 65535.0f);
        sp_s[c]  = scales[nBase + c] * (1.0f / 127.0f);
        b_s[c]   = bias[nBase + c];
    }

    float acc[4][8][4];
#pragma unroll
    for (int i = 0; i < 4; i++)
#pragma unroll
        for (int j = 0; j < 8; j++)
#pragma unroll
            for (int k = 0; k < 4; k++) acc[i][j][k] = 0.f;

    auto fill = [&](int s, int kt) {
        size_t koff = (size_t)kt * 64;           // elements
        uint32_t base = sb + OFF_ST + s * STAGE;
#pragma unroll
        for (int i = 0; i < 16; i++) {
            int id = tid + i * 128;
            bool isB = id >= BM * 8;
            int li2 = isB ? id - BM * 8 : id;
            int r = li2 >> 3, c = li2 & 7;
            const __nv_bfloat16* src =
                (isB ? W + (nBase + r) * (size_t)K_DIM
                     : X + (mBase + r) * (size_t)K_DIM) + koff + c * 8;
            cp16(base + (isB ? BM * ASTR : 0) + r * ASTR + c * 16, src);
        }
        asm volatile("cp.async.commit_group;" ::: "memory");
    };

    fill(0, 0);
    fill(1, 1);
    const int KT = K_DIM / 64;   // 64
    const int lg = lane >> 3, li = lane & 7;
    const int aRow = wm * 64, bRow = wn * 64;

    for (int kt = 0; kt < KT; kt++) {
        int s = kt % 3;
        asm volatile("cp.async.wait_group 1;" ::: "memory");
        __syncthreads();
        if (kt + 2 < KT) fill((kt + 2) % 3, kt + 2);
        else asm volatile("cp.async.commit_group;" ::: "memory");

        uint32_t Ab = sb + OFF_ST + s * STAGE;
        uint32_t Bb = Ab + BM * ASTR;

        uint32_t a[2][4][4], b[2][8][2];
        ldfragsA(a[0], Ab, aRow, 0, lg, li);
        ldfragsB(b[0], Bb, bRow, 0, lg, li);
#pragma unroll
        for (int k16 = 0; k16 < 4; k16++) {
            int cur = k16 & 1, nxt = cur ^ 1;
            if (k16 < 3) {
                ldfragsA(a[nxt], Ab, aRow, (k16 + 1) * 32, lg, li);
                ldfragsB(b[nxt], Bb, bRow, (k16 + 1) * 32, lg, li);
            }
#pragma unroll
            for (int mt = 0; mt < 4; mt++)
#pragma unroll
                for (int nt = 0; nt < 8; nt++)
                    mma16(acc[mt][nt], a[cur][mt], b[cur][nt]);
        }
    }
    asm volatile("cp.async.wait_group 0;" ::: "memory");
    __syncthreads();

    // Fused epilogue
    const int t4 = lane >> 2, t2 = (lane & 3) * 2;
#pragma unroll
    for (int mt = 0; mt < 4; mt++) {
#pragma unroll
        for (int p = 0; p < 2; p++) {
            size_t m = mBase + wm * 64 + mt * 16 + t4 + p * 8;
#pragma unroll
            for (int nt = 0; nt < 8; nt++) {
                int nl = wn * 64 + nt * 8 + t2;
                size_t n = nBase + nl;
                float v0 = fmaf(sp_s[nl], acc[mt][nt][2 * p + 0],
                           fmaf(r_s[nl],
                                __ldg(&Pt[(size_t)idx_s[nl] * Mtot + m]), b_s[nl]));
                float v1 = fmaf(sp_s[nl + 1], acc[mt][nt][2 * p + 1],
                           fmaf(r_s[nl + 1],
                                __ldg(&Pt[(size_t)idx_s[nl + 1] * Mtot + m]), b_s[nl + 1]));
                *(float2*)(Y + m * (size_t)N + n) = make_float2(v0, v1);
            }
        }
    }
}

// ---------------------------------------------------------------------------
// P GEMM (bf16, 3 virtual passes = 192 k-steps, SPLIT-K over blockIdx.z):
//   out[b][m] = partial sum over kt in [kt0, kt1) of Ap[pass][b] . Bp[pass][m]
// CTA tile 128x128x64, 128 threads (2x2 warps, warp tile 64x64).
// grid (M/128, NBASIS/128, 2) = 256 CTAs -> ~2 CTAs/SM in one wave.
// ---------------------------------------------------------------------------

__global__ __launch_bounds__(128, 2)
void gemm_P(const __nv_bfloat16* __restrict__ Bhi, const __nv_bfloat16* __restrict__ Blo,
            const __nv_bfloat16* __restrict__ Xhi, const __nv_bfloat16* __restrict__ Xlo,
            float* __restrict__ PtA, float* __restrict__ PtB, int Mtot)
{
    constexpr int BM = 128, BN = 128;
    constexpr int STAGE = (BM + BN) * ASTR;      // 36864
    constexpr int KT_TOTAL = 3 * (K_DIM / 64);   // 192
    constexpr int KT_HALF  = KT_TOTAL / 2;       // 96
    extern __shared__ char smem[];
    const int tid = threadIdx.x, lane = tid & 31, wid = tid >> 5;
    const int wm = wid & 1, wn = wid >> 1;       // 2 x 2 warps, warp tile 64x64
    const size_t mBase = (size_t)blockIdx.y * BM;    // basis dim
    const size_t nBase = (size_t)blockIdx.x * BN;    // token dim
    const int kt0 = blockIdx.z * KT_HALF;
    const int kt1 = kt0 + KT_HALF;
    float* out = (blockIdx.z == 0) ? PtA : PtB;
    const uint32_t sb = (uint32_t)__cvta_generic_to_shared(smem);

    float acc[4][8][4];
#pragma unroll
    for (int i = 0; i < 4; i++)
#pragma unroll
        for (int j = 0; j < 8; j++)
#pragma unroll
            for (int k = 0; k < 4; k++) acc[i][j][k] = 0.f;

    const __nv_bfloat16* Ap[3] = {Bhi, Blo, Bhi};
    const __nv_bfloat16* Bp[3] = {Xhi, Xhi, Xlo};

    auto fill = [&](int s, int kt) {
        int pass = kt >> 6;                      // 64 k-steps per pass
        const __nv_bfloat16* A = Ap[pass];
        const __nv_bfloat16* B = Bp[pass];
        size_t koff = (size_t)(kt & 63) * 64;
        uint32_t base = sb + s * STAGE;
#pragma unroll
        for (int i = 0; i < 16; i++) {
            int id = tid + i * 128;
            bool isB = id >= BM * 8;
            int li2 = isB ? id - BM * 8 : id;
            int r = li2 >> 3, c = li2 & 7;
            const __nv_bfloat16* src =
                (isB ? B + (nBase + r) * (size_t)K_DIM
                     : A + (mBase + r) * (size_t)K_DIM) + koff + c * 8;
            cp16(base + (isB ? BM * ASTR : 0) + r * ASTR + c * 16, src);
        }
        asm volatile("cp.async.commit_group;" ::: "memory");
    };

    fill(0, kt0);
    fill(1, kt0 + 1);
    const int lg = lane >> 3, li = lane & 7;
    const int aRow = wm * 64, bRow = wn * 64;

    for (int kt = kt0; kt < kt1; kt++) {
        int j = kt - kt0;
        int s = j % 3;
        asm volatile("cp.async.wait_group 1;" ::: "memory");
        __syncthreads();
        if (kt + 2 < kt1) fill((j + 2) % 3, kt + 2);
        else asm volatile("cp.async.commit_group;" ::: "memory");

        uint32_t Ab = sb + s * STAGE;
        uint32_t Bb = Ab + BM * ASTR;

        uint32_t a[2][4][4], b[2][8][2];
        ldfragsA(a[0], Ab, aRow, 0, lg, li);
        ldfragsB(b[0], Bb, bRow, 0, lg, li);
#pragma unroll
        for (int k16 = 0; k16 < 4; k16++) {
            int cur = k16 & 1, nxt = cur ^ 1;
            if (k16 < 3) {
                ldfragsA(a[nxt], Ab, aRow, (k16 + 1) * 32, lg, li);
                ldfragsB(b[nxt], Bb, bRow, (k16 + 1) * 32, lg, li);
            }
#pragma unroll
            for (int mt = 0; mt < 4; mt++)
#pragma unroll
                for (int nt = 0; nt < 8; nt++)
                    mma16(acc[mt][nt], a[cur][mt], b[cur][nt]);
        }
    }
    asm volatile("cp.async.wait_group 0;" ::: "memory");
    __syncthreads();

    const int t4 = lane >> 2, t2 = (lane & 3) * 2;
#pragma unroll
    for (int mt = 0; mt < 4; mt++) {
#pragma unroll
        for (int p = 0; p < 2; p++) {
            size_t bg = mBase + wm * 64 + mt * 16 + t4 + p * 8;
#pragma unroll
            for (int nt = 0; nt < 8; nt++) {
                size_t mcol = nBase + wn * 64 + nt * 8 + t2;
                *(float2*)(out + bg * (size_t)Mtot + mcol) =
                    make_float2(acc[mt][nt][2 * p + 0], acc[mt][nt][2 * p + 1]);
            }
        }
    }
}

// ---------------------------------------------------------------------------
// Launch
// ---------------------------------------------------------------------------

extern "C" void kernel_launch(void* const* d_in, const int* in_sizes, int n_in,
                              void* d_out, int out_size) {
    const float* x      = (const float*)d_in[0];
    const int*   codes  = (const int*)d_in[1];
    const float* basis  = (const float*)d_in[2];
    const int*   residq = (const int*)d_in[3];
    const float* scales = (const float*)d_in[4];
    const float* bias   = (const float*)d_in[5];
    float*       y      = (float*)d_out;

    int N = in_sizes[1];                 // 4096
    int K = in_sizes[2] / NBASIS;        // 4096
    int M = in_sizes[0] / K;             // 8192

    __nv_bfloat16 *Xhi, *Xlo, *Wres, *Bhi, *Blo;
    float *Pt, *PtA, *PtB;
    cudaGetSymbolAddress((void**)&Xhi,  g_Xhi);
    cudaGetSymbolAddress((void**)&Xlo,  g_Xlo);
    cudaGetSymbolAddress((void**)&Wres, g_Wres);
    cudaGetSymbolAddress((void**)&Bhi,  g_Bhi);
    cudaGetSymbolAddress((void**)&Blo,  g_Blo);
    cudaGetSymbolAddress((void**)&Pt,   g_Pt);
    cudaGetSymbolAddress((void**)&PtA,  g_PtA);
    cudaGetSymbolAddress((void**)&PtB,  g_PtB);

    constexpr int SMEM_BIG = 2048 + 3 * (128 + 128) * ASTR;  // 112640
    constexpr int SMEM_P   = 3 * (128 + 128) * ASTR;         // 110592
    cudaFuncSetAttribute(gemm_big, cudaFuncAttributeMaxDynamicSharedMemorySize, SMEM_BIG);
    cudaFuncSetAttribute(gemm_P,   cudaFuncAttributeMaxDynamicSharedMemorySize, SMEM_P);

    // 1) Preprocess: split x and basis into bf16 hi/lo; residual -> exact bf16 ints
    int nx4 = (M * K) / 4;
    prep_x<<<(nx4 + 255) / 256, 256>>>(x, Xhi, Xlo, nx4);
    int nb4 = (NBASIS * K) / 4;
    prep_x<<<(nb4 + 255) / 256, 256>>>(basis, Bhi, Blo, nb4);
    int nw4 = (N * K) / 4;
    prep_w<<<(nw4 + 255) / 256, 256>>>(residq, Wres, nw4);

    // 2) P GEMM, split-K over z: partials PtA (kt 0..95), PtB (kt 96..191)
    gemm_P<<<dim3(M / 128, NBASIS / 128, 2), 128, SMEM_P>>>(
        Bhi, Blo, Xhi, Xlo, PtA, PtB, M);

    // 2b) Reduce: Pt = PtA + PtB
    int nr4 = (NBASIS * M) / 4;
    reduce_Pt<<<(nr4 + 255) / 256, 256>>>(PtA, PtB, Pt, nr4);

    // 3) Big GEMM + fused bitfield epilogue:
    //    y[m][o] = (scales[o]/127)*(Xhi.Wres[o]) + r[o]*Pt[idx[o]][m] + bias[o]
    gemm_big<<<dim3(N / 128, M / 128), 128, SMEM_BIG>>>(
        Xhi, Wres, y, codes, scales, bias, Pt, N, M);
}

// round 12
// speedup vs baseline: 1.1925x; 1.0279x over previous
#include <cuda_runtime.h>
#include <cuda_bf16.h>
#include <cstdint>

// Problem constants (fixed by the dataset)
#define M_MAX   8192
#define K_DIM   4096
#define N_DIM   4096
#define NBASIS  256

// Scratch (static device arrays — no allocation allowed)
__device__ __nv_bfloat16 g_Xhi[M_MAX * K_DIM];
__device__ __nv_bfloat16 g_Xlo[M_MAX * K_DIM];
__device__ __nv_bfloat16 g_Wres[N_DIM * K_DIM];
__device__ __nv_bfloat16 g_Bhi[NBASIS * K_DIM];
__device__ __nv_bfloat16 g_Blo[NBASIS * K_DIM];
__device__ float         g_Pt [NBASIS * M_MAX];  // Pt[basis][m]

// ---------------------------------------------------------------------------
// Prep kernels
// ---------------------------------------------------------------------------

__global__ void prep_x(const float* __restrict__ x,
                       __nv_bfloat16* __restrict__ hi,
                       __nv_bfloat16* __restrict__ lo, int n4) {
    int i = blockIdx.x * blockDim.x + threadIdx.x;
    if (i >= n4) return;
    float4 v = ((const float4*)x)[i];
    __nv_bfloat162 h01 = __floats2bfloat162_rn(v.x, v.y);
    __nv_bfloat162 h23 = __floats2bfloat162_rn(v.z, v.w);
    ((__nv_bfloat162*)hi)[2 * i]     = h01;
    ((__nv_bfloat162*)hi)[2 * i + 1] = h23;
    float l0 = v.x - __bfloat162float(h01.x);
    float l1 = v.y - __bfloat162float(h01.y);
    float l2 = v.z - __bfloat162float(h23.x);
    float l3 = v.w - __bfloat162float(h23.y);
    ((__nv_bfloat162*)lo)[2 * i]     = __floats2bfloat162_rn(l0, l1);
    ((__nv_bfloat162*)lo)[2 * i + 1] = __floats2bfloat162_rn(l2, l3);
}

__global__ void prep_w(const int* __restrict__ q,
                       __nv_bfloat16* __restrict__ w, int n4) {
    int i = blockIdx.x * blockDim.x + threadIdx.x;
    if (i >= n4) return;
    int4 v = ((const int4*)q)[i];
    // q - 128 is an integer in [-128,127]: exactly representable in bf16.
    __nv_bfloat162 w01 = __floats2bfloat162_rn((float)(v.x - 128), (float)(v.y - 128));
    __nv_bfloat162 w23 = __floats2bfloat162_rn((float)(v.z - 128), (float)(v.w - 128));
    ((__nv_bfloat162*)w)[2 * i]     = w01;
    ((__nv_bfloat162*)w)[2 * i + 1] = w23;
}

// ---------------------------------------------------------------------------
// MMA helpers (legacy HMMA pipe: ldmatrix + mma.sync.m16n8k16.bf16 + cp.async)
// ---------------------------------------------------------------------------

__device__ __forceinline__ void ldsm4(uint32_t& r0, uint32_t& r1,
                                      uint32_t& r2, uint32_t& r3, uint32_t a) {
    asm volatile("ldmatrix.sync.aligned.m8n8.x4.shared.b16 {%0,%1,%2,%3}, [%4];"
                 : "=r"(r0), "=r"(r1), "=r"(r2), "=r"(r3) : "r"(a));
}

__device__ __forceinline__ void mma16(float* c, const uint32_t* a, const uint32_t* b) {
    asm volatile(
        "mma.sync.aligned.m16n8k16.row.col.f32.bf16.bf16.f32 "
        "{%0,%1,%2,%3},{%4,%5,%6,%7},{%8,%9},{%0,%1,%2,%3};"
        : "+f"(c[0]), "+f"(c[1]), "+f"(c[2]), "+f"(c[3])
        : "r"(a[0]), "r"(a[1]), "r"(a[2]), "r"(a[3]), "r"(b[0]), "r"(b[1]));
}

__device__ __forceinline__ void cp16(uint32_t s, const void* g) {
    asm volatile("cp.async.cg.shared.global [%0], [%1], 16;" :: "r"(s), "l"(g));
}

#define ASTR 144   // 128B of K (64 bf16) + 16B pad: conflict-free ldmatrix phases

// Fragment loaders. a4: 4 m16-frags (64 rows); a2: 2 m16-frags (32 rows);
// b8: 8 n8-frags (64 rows) loaded pairwise via ldsm.x4.
__device__ __forceinline__ void ldfragsA4(uint32_t (*a)[4], uint32_t Ab, int rowBase,
                                          int kb, int lg, int li) {
#pragma unroll
    for (int mt = 0; mt < 4; mt++) {
        int row = rowBase + mt * 16 + li + (lg & 1) * 8;
        ldsm4(a[mt][0], a[mt][1], a[mt][2], a[mt][3],
              Ab + row * ASTR + kb + (lg >> 1) * 16);
    }
}
__device__ __forceinline__ void ldfragsA2(uint32_t (*a)[4], uint32_t Ab, int rowBase,
                                          int kb, int lg, int li) {
#pragma unroll
    for (int mt = 0; mt < 2; mt++) {
        int row = rowBase + mt * 16 + li + (lg & 1) * 8;
        ldsm4(a[mt][0], a[mt][1], a[mt][2], a[mt][3],
              Ab + row * ASTR + kb + (lg >> 1) * 16);
    }
}
__device__ __forceinline__ void ldfragsB8(uint32_t (*b)[2], uint32_t Bb, int rowBase,
                                          int kb, int lg, int li) {
#pragma unroll
    for (int g = 0; g < 4; g++) {
        int row = rowBase + g * 16 + li + (lg >> 1) * 8;
        uint32_t r0, r1, r2, r3;
        ldsm4(r0, r1, r2, r3, Bb + row * ASTR + kb + (lg & 1) * 16);
        b[2 * g][0] = r0; b[2 * g][1] = r1;
        b[2 * g + 1][0] = r2; b[2 * g + 1][1] = r3;
    }
}

// ---------------------------------------------------------------------------
// Big GEMM (bf16): acc = Xhi[m] . Wres[o]  +  fused bitfield epilogue:
//   y[m][o] = sp[o]*acc + r[o]*Pt[idx[o]][m] + bias[o]
// CTA tile 128x128x64(elems), 128 threads (2x2 warps, warp tile 64x64),
// 3-stage cp.async pipeline, register-double-buffered fragments, 2 CTAs/SM.
// (unchanged — proven config)
// ---------------------------------------------------------------------------

__global__ __launch_bounds__(128, 2)
void gemm_big(const __nv_bfloat16* __restrict__ X, const __nv_bfloat16* __restrict__ W,
              float* __restrict__ Y,
              const int* __restrict__ codes, const float* __restrict__ scales,
              const float* __restrict__ bias, const float* __restrict__ Pt,
              int N, int Mtot)
{
    constexpr int BM = 128, BN = 128;            // rows; row = 64 bf16 = 128B
    constexpr int STAGE = (BM + BN) * ASTR;      // 36864
    constexpr int OFF_ST = 2048;
    extern __shared__ char smem[];
    const int tid = threadIdx.x, lane = tid & 31, wid = tid >> 5;
    const int wm = wid & 1, wn = wid >> 1;       // 2 x 2 warps, warp tile 64x64
    const size_t mBase = (size_t)blockIdx.y * BM;
    const size_t nBase = (size_t)blockIdx.x * BN;
    const uint32_t sb = (uint32_t)__cvta_generic_to_shared(smem);

    // decode per-column params into smem
    int*   idx_s = (int*)smem;
    float* r_s   = (float*)smem + BN;
    float* sp_s  = (float*)smem + 2 * BN;
    float* b_s   = (float*)smem + 3 * BN;
    for (int c = tid; c < BN; c += 128) {
        int code = codes[nBase + c];
        idx_s[c] = code & 0xFF;
        r_s[c]   = (float)((code >> 8) & 0xFFFF) * (1.0f / 65535.0f);
        sp_s[c]  = scales[nBase + c] * (1.0f / 127.0f);
        b_s[c]   = bias[nBase + c];
    }

    float acc[4][8][4];
#pragma unroll
    for (int i = 0; i < 4; i++)
#pragma unroll
        for (int j = 0; j < 8; j++)
#pragma unroll
            for (int k = 0; k < 4; k++) acc[i][j][k] = 0.f;

    auto fill = [&](int s, int kt) {
        size_t koff = (size_t)kt * 64;           // elements
        uint32_t base = sb + OFF_ST + s * STAGE;
#pragma unroll
        for (int i = 0; i < 16; i++) {
            int id = tid + i * 128;
            bool isB = id >= BM * 8;
            int li2 = isB ? id - BM * 8 : id;
            int r = li2 >> 3, c = li2 & 7;
            const __nv_bfloat16* src =
                (isB ? W + (nBase + r) * (size_t)K_DIM
                     : X + (mBase + r) * (size_t)K_DIM) + koff + c * 8;
            cp16(base + (isB ? BM * ASTR : 0) + r * ASTR + c * 16, src);
        }
        asm volatile("cp.async.commit_group;" ::: "memory");
    };

    fill(0, 0);
    fill(1, 1);
    const int KT = K_DIM / 64;   // 64
    const int lg = lane >> 3, li = lane & 7;
    const int aRow = wm * 64, bRow = wn * 64;

    for (int kt = 0; kt < KT; kt++) {
        int s = kt % 3;
        asm volatile("cp.async.wait_group 1;" ::: "memory");
        __syncthreads();
        if (kt + 2 < KT) fill((kt + 2) % 3, kt + 2);
        else asm volatile("cp.async.commit_group;" ::: "memory");

        uint32_t Ab = sb + OFF_ST + s * STAGE;
        uint32_t Bb = Ab + BM * ASTR;

        uint32_t a[2][4][4], b[2][8][2];
        ldfragsA4(a[0], Ab, aRow, 0, lg, li);
        ldfragsB8(b[0], Bb, bRow, 0, lg, li);
#pragma unroll
        for (int k16 = 0; k16 < 4; k16++) {
            int cur = k16 & 1, nxt = cur ^ 1;
            if (k16 < 3) {
                ldfragsA4(a[nxt], Ab, aRow, (k16 + 1) * 32, lg, li);
                ldfragsB8(b[nxt], Bb, bRow, (k16 + 1) * 32, lg, li);
            }
#pragma unroll
            for (int mt = 0; mt < 4; mt++)
#pragma unroll
                for (int nt = 0; nt < 8; nt++)
                    mma16(acc[mt][nt], a[cur][mt], b[cur][nt]);
        }
    }
    asm volatile("cp.async.wait_group 0;" ::: "memory");
    __syncthreads();

    // Fused epilogue
    const int t4 = lane >> 2, t2 = (lane & 3) * 2;
#pragma unroll
    for (int mt = 0; mt < 4; mt++) {
#pragma unroll
        for (int p = 0; p < 2; p++) {
            size_t m = mBase + wm * 64 + mt * 16 + t4 + p * 8;
#pragma unroll
            for (int nt = 0; nt < 8; nt++) {
                int nl = wn * 64 + nt * 8 + t2;
                size_t n = nBase + nl;
                float v0 = fmaf(sp_s[nl], acc[mt][nt][2 * p + 0],
                           fmaf(r_s[nl],
                                __ldg(&Pt[(size_t)idx_s[nl] * Mtot + m]), b_s[nl]));
                float v1 = fmaf(sp_s[nl + 1], acc[mt][nt][2 * p + 1],
                           fmaf(r_s[nl + 1],
                                __ldg(&Pt[(size_t)idx_s[nl + 1] * Mtot + m]), b_s[nl + 1]));
                *(float2*)(Y + m * (size_t)N + n) = make_float2(v0, v1);
            }
        }
    }
}

// ---------------------------------------------------------------------------
// P GEMM, FUSED 3-pass (single k-sweep):
//   Pt[b][m] = Bhi[b].Xhi[m] + Blo[b].Xhi[m] + Bhi[b].Xlo[m]
// Each stage holds {Ahi, Alo} (64 basis rows each) + {Xhi, Xlo} (128 token
// rows each) for one 64-elem k-chunk; all three products accumulate into one
// fp32 accumulator. X fetched ONCE. CTA tile 64(basis)x128(tokens), 128
// threads (2x2 warps, warp tile 32x64), 2-stage pipeline, 2 CTAs/SM.
// grid (M/128, NBASIS/64) = 256 CTAs -> one <=2/SM wave, no split-K.
// ---------------------------------------------------------------------------

__global__ __launch_bounds__(128, 2)
void gemm_P(const __nv_bfloat16* __restrict__ Bh, const __nv_bfloat16* __restrict__ Bl,
            const __nv_bfloat16* __restrict__ Xh, const __nv_bfloat16* __restrict__ Xl,
            float* __restrict__ Pt, int Mtot)
{
    constexpr int BA = 64;                        // basis rows per CTA
    constexpr int BT = 128;                       // token cols per CTA
    constexpr int OFF_AHI = 0;
    constexpr int OFF_ALO = BA * ASTR;            // 9216
    constexpr int OFF_XHI = 2 * BA * ASTR;        // 18432
    constexpr int OFF_XLO = OFF_XHI + BT * ASTR;  // 36864
    constexpr int STAGE   = OFF_XLO + BT * ASTR;  // 55296
    extern __shared__ char smem[];
    const int tid = threadIdx.x, lane = tid & 31, wid = tid >> 5;
    const int wm = wid & 1, wn = wid >> 1;        // warp tile: 32 basis x 64 tokens
    const size_t aBase = (size_t)blockIdx.y * BA; // basis dim
    const size_t nBase = (size_t)blockIdx.x * BT; // token dim
    const uint32_t sb = (uint32_t)__cvta_generic_to_shared(smem);

    float acc[2][8][4];
#pragma unroll
    for (int i = 0; i < 2; i++)
#pragma unroll
        for (int j = 0; j < 8; j++)
#pragma unroll
            for (int k = 0; k < 4; k++) acc[i][j][k] = 0.f;

    auto fill = [&](int s, int kt) {
        size_t koff = (size_t)kt * 64;
        uint32_t base = sb + s * STAGE;
#pragma unroll
        for (int i = 0; i < 24; i++) {
            int id = tid + i * 128;               // 0..3071
            int c = id & 7;
            const __nv_bfloat16* src;
            uint32_t dst;
            if (id < 512) {
                int rr = id >> 3;
                src = Bh + (aBase + rr) * (size_t)K_DIM;
                dst = base + OFF_AHI + rr * ASTR;
            } else if (id < 1024) {
                int rr = (id - 512) >> 3;
                src = Bl + (aBase + rr) * (size_t)K_DIM;
                dst = base + OFF_ALO + rr * ASTR;
            } else if (id < 2048) {
                int rr = (id - 1024) >> 3;
                src = Xh + (nBase + rr) * (size_t)K_DIM;
                dst = base + OFF_XHI + rr * ASTR;
            } else {
                int rr = (id - 2048) >> 3;
                src = Xl + (nBase + rr) * (size_t)K_DIM;
                dst = base + OFF_XLO + rr * ASTR;
            }
            cp16(dst + c * 16, src + koff + c * 8);
        }
        asm volatile("cp.async.commit_group;" ::: "memory");
    };

    fill(0, 0);
    fill(1, 1);
    const int KT = K_DIM / 64;   // 64
    const int lg = lane >> 3, li = lane & 7;
    const int aRow = wm * 32, bRow = wn * 64;

    for (int kt = 0; kt < KT; kt++) {
        int s = kt & 1;
        asm volatile("cp.async.wait_group 1;" ::: "memory");
        __syncthreads();

        uint32_t Ah = sb + s * STAGE + OFF_AHI;
        uint32_t Al = sb + s * STAGE + OFF_ALO;
        uint32_t Xhb = sb + s * STAGE + OFF_XHI;
        uint32_t Xlb = sb + s * STAGE + OFF_XLO;

        uint32_t ah[2][2][4], al[2][2][4], xh[2][8][2], xl[2][8][2];
        ldfragsA2(ah[0], Ah, aRow, 0, lg, li);
        ldfragsA2(al[0], Al, aRow, 0, lg, li);
        ldfragsB8(xh[0], Xhb, bRow, 0, lg, li);
        ldfragsB8(xl[0], Xlb, bRow, 0, lg, li);
#pragma unroll
        for (int k16 = 0; k16 < 4; k16++) {
            int cur = k16 & 1, nxt = cur ^ 1;
            if (k16 < 3) {
                int kb = (k16 + 1) * 32;
                ldfragsA2(ah[nxt], Ah, aRow, kb, lg, li);
                ldfragsA2(al[nxt], Al, aRow, kb, lg, li);
                ldfragsB8(xh[nxt], Xhb, bRow, kb, lg, li);
                ldfragsB8(xl[nxt], Xlb, bRow, kb, lg, li);
            }
#pragma unroll
            for (int mt = 0; mt < 2; mt++)
#pragma unroll
                for (int nt = 0; nt < 8; nt++) {
                    mma16(acc[mt][nt], ah[cur][mt], xh[cur][nt]);  // hi.hi
                    mma16(acc[mt][nt], al[cur][mt], xh[cur][nt]);  // lo.hi
                    mma16(acc[mt][nt], ah[cur][mt], xl[cur][nt]);  // hi.lo
                }
        }
        __syncthreads();   // all warps done reading stage s before refilling it
        if (kt + 2 < KT) fill(s, kt + 2);
        else asm volatile("cp.async.commit_group;" ::: "memory");
    }
    asm volatile("cp.async.wait_group 0;" ::: "memory");
    __syncthreads();

    const int t4 = lane >> 2, t2 = (lane & 3) * 2;
#pragma unroll
    for (int mt = 0; mt < 2; mt++) {
#pragma unroll
        for (int p = 0; p < 2; p++) {
            size_t bg = aBase + wm * 32 + mt * 16 + t4 + p * 8;
#pragma unroll
            for (int nt = 0; nt < 8; nt++) {
                size_t mcol = nBase + wn * 64 + nt * 8 + t2;
                *(float2*)(Pt + bg * (size_t)Mtot + mcol) =
                    make_float2(acc[mt][nt][2 * p + 0], acc[mt][nt][2 * p + 1]);
            }
        }
    }
}

// ---------------------------------------------------------------------------
// Launch
// ---------------------------------------------------------------------------

extern "C" void kernel_launch(void* const* d_in, const int* in_sizes, int n_in,
                              void* d_out, int out_size) {
    const float* x      = (const float*)d_in[0];
    const int*   codes  = (const int*)d_in[1];
    const float* basis  = (const float*)d_in[2];
    const int*   residq = (const int*)d_in[3];
    const float* scales = (const float*)d_in[4];
    const float* bias   = (const float*)d_in[5];
    float*       y      = (float*)d_out;

    int N = in_sizes[1];                 // 4096
    int K = in_sizes[2] / NBASIS;        // 4096
    int M = in_sizes[0] / K;             // 8192

    __nv_bfloat16 *Xhi, *Xlo, *Wres, *Bhi, *Blo;
    float* Pt;
    cudaGetSymbolAddress((void**)&Xhi,  g_Xhi);
    cudaGetSymbolAddress((void**)&Xlo,  g_Xlo);
    cudaGetSymbolAddress((void**)&Wres, g_Wres);
    cudaGetSymbolAddress((void**)&Bhi,  g_Bhi);
    cudaGetSymbolAddress((void**)&Blo,  g_Blo);
    cudaGetSymbolAddress((void**)&Pt,   g_Pt);

    constexpr int SMEM_BIG = 2048 + 3 * (128 + 128) * ASTR;  // 112640
    constexpr int SMEM_P   = 2 * (64 + 64 + 128 + 128) * ASTR; // 110592
    cudaFuncSetAttribute(gemm_big, cudaFuncAttributeMaxDynamicSharedMemorySize, SMEM_BIG);
    cudaFuncSetAttribute(gemm_P,   cudaFuncAttributeMaxDynamicSharedMemorySize, SMEM_P);

    // 1) Preprocess: split x and basis into bf16 hi/lo; residual -> exact bf16 ints
    int nx4 = (M * K) / 4;
    prep_x<<<(nx4 + 255) / 256, 256>>>(x, Xhi, Xlo, nx4);
    int nb4 = (NBASIS * K) / 4;
    prep_x<<<(nb4 + 255) / 256, 256>>>(basis, Bhi, Blo, nb4);
    int nw4 = (N * K) / 4;
    prep_w<<<(nw4 + 255) / 256, 256>>>(residq, Wres, nw4);

    // 2) P GEMM, fused 3-pass single sweep: Pt[b][m] = Bhi.Xhi + Blo.Xhi + Bhi.Xlo
    gemm_P<<<dim3(M / 128, NBASIS / 64), 128, SMEM_P>>>(
        Bhi, Blo, Xhi, Xlo, Pt, M);

    // 3) Big GEMM + fused bitfield epilogue:
    //    y[m][o] = (scales[o]/127)*(Xhi.Wres[o]) + r[o]*Pt[idx[o]][m] + bias[o]
    gemm_big<<<dim3(N / 128, M / 128), 128, SMEM_BIG>>>(
        Xhi, Wres, y, codes, scales, bias, Pt, N, M);
}